// round 2
// baseline (speedup 1.0000x reference)
#include <cuda_runtime.h>
#include <math.h>

#define T_MAX 1000
#define B_ 64
#define D_ 128
#define N_ 512
#define O_ 10

// scratch (device globals: no allocation allowed in kernel_launch)
__device__ float g_Iext[(size_t)T_MAX * B_ * N_];  // 131 MB
__device__ float g_WT[N_ * N_];                    // W_rec transposed: g_WT[m][n] = W_rec[n][m]

// ---------------- transpose W_rec -> g_WT ----------------
__global__ void wt_transpose(const float* __restrict__ W) {
    __shared__ float tile[32][33];
    int bx = blockIdx.x * 32, by = blockIdx.y * 32;
    int tx = threadIdx.x, ty = threadIdx.y;
#pragma unroll
    for (int i = 0; i < 32; i += 8)
        tile[ty + i][tx] = W[(size_t)(by + ty + i) * N_ + (bx + tx)];
    __syncthreads();
#pragma unroll
    for (int i = 0; i < 32; i += 8)
        g_WT[(size_t)(bx + ty + i) * N_ + (by + tx)] = tile[tx][ty + i];
}

// ---------------- I_ext GEMM: (T*B,128) x (128,512) fp32, packed f32x2 FMA ----------------
#define GBM 128
#define GBN 128
#define GK  128
#define A_LD 132
#define B_LD 130
#define GEMM_SMEM ((GBM * A_LD + GK * B_LD) * 4)

__global__ __launch_bounds__(256) void iext_gemm(const float* __restrict__ X,
                                                 const float* __restrict__ Win,
                                                 const float* __restrict__ sc_p) {
    extern __shared__ float sm[];
    float* As = sm;                 // [GBM][A_LD]  m-major
    float* Bs = sm + GBM * A_LD;    // [GK][B_LD]   k-major (W_in transposed)
    const float sc = __ldg(sc_p);
    const int m0 = blockIdx.x * GBM;
    const int n0 = blockIdx.y * GBN;
    const int tid = threadIdx.x;
    const int lane4 = (tid & 31) * 4;
    const int wrp = tid >> 5;

    // load A tile (rows of x, scaled), direct m-major, conflict-free float4 stores
#pragma unroll
    for (int p = 0; p < 16; ++p) {
        int m = wrp + p * 8;
        float4 xv = *(const float4*)(X + (size_t)(m0 + m) * D_ + lane4);
        xv.x *= sc; xv.y *= sc; xv.z *= sc; xv.w *= sc;
        *(float4*)(As + m * A_LD + lane4) = xv;
    }
    // load B tile (W_in rows), transposed to k-major
#pragma unroll
    for (int p = 0; p < 16; ++p) {
        int nn = wrp + p * 8;
        float4 wv = *(const float4*)(Win + (size_t)(n0 + nn) * D_ + lane4);
        Bs[(lane4 + 0) * B_LD + nn] = wv.x;
        Bs[(lane4 + 1) * B_LD + nn] = wv.y;
        Bs[(lane4 + 2) * B_LD + nn] = wv.z;
        Bs[(lane4 + 3) * B_LD + nn] = wv.w;
    }
    __syncthreads();

    const int tm  = (tid >> 4) * 8;   // 8 M-rows per thread
    const int tn2 = (tid & 15) * 2;   // 8 N-cols as 4 float2 at stride 32 (bank-conflict-free)
    unsigned long long acc[8][4];
#pragma unroll
    for (int i = 0; i < 8; ++i)
#pragma unroll
        for (int j = 0; j < 4; ++j) acc[i][j] = 0ull;

#pragma unroll 2
    for (int k = 0; k < GK; ++k) {
        unsigned long long b2[4];
#pragma unroll
        for (int j = 0; j < 4; ++j) {
            float2 bb = *(const float2*)(Bs + k * B_LD + tn2 + 32 * j);
            asm("mov.b64 %0, {%1,%2};" : "=l"(b2[j]) : "f"(bb.x), "f"(bb.y));
        }
#pragma unroll
        for (int i = 0; i < 8; ++i) {
            float a = As[(tm + i) * A_LD + k];
            unsigned long long a2;
            asm("mov.b64 %0, {%1,%1};" : "=l"(a2) : "f"(a));
#pragma unroll
            for (int j = 0; j < 4; ++j)
                asm("fma.rn.f32x2 %0, %1, %2, %0;" : "+l"(acc[i][j]) : "l"(a2), "l"(b2[j]));
        }
    }
#pragma unroll
    for (int i = 0; i < 8; ++i) {
        float* orow = g_Iext + (size_t)(m0 + tm + i) * N_ + n0 + tn2;
#pragma unroll
        for (int j = 0; j < 4; ++j) {
            float2 o;
            asm("mov.b64 {%0,%1}, %2;" : "=f"(o.x), "=f"(o.y) : "l"(acc[i][j]));
            *(float2*)(orow + 32 * j) = o;
        }
    }
}

// ---------------- recurrent GLIF3 simulation: 1 CTA per batch, 1 thread per neuron ----------------
__global__ __launch_bounds__(512, 1) void sim_kernel(
    const float* __restrict__ Wout, const float* __restrict__ bout,
    const float* __restrict__ osc_p,
    float* __restrict__ out, float* __restrict__ spk, float* __restrict__ vlt,
    float* __restrict__ pscO, float* __restrict__ filt,
    int T, int startT, int writeHist,
    float e_syn, float e_asc, float alpha)
{
    const int b = blockIdx.x;
    const int n = threadIdx.x;
    const int wid = n >> 5, lane = n & 31;
    __shared__ unsigned smask[2][16];   // double-buffered spike bitmasks
    __shared__ float sred[16];
    if (n < 16) smask[0][n] = 0u;
    __syncthreads();

    const float a_mem = 0.05f, VR = -60.0f, VTH = -45.0f, KP = 0.2f, AA = -0.2f;
    const float oma = 1.0f - alpha;
    float v = VR, asc = 0.f, r = 0.f, psc = 0.f, f = 0.f, fsum = 0.f;
    int rcnt = 0;
    const float* Ibase = g_Iext + (size_t)b * N_ + n;
    const float* WTn = g_WT + n;

    for (int t = 0; t < T; ++t) {
        const int buf = t & 1;
        float It = __ldg(Ibase + (size_t)t * (B_ * N_));

        // sparse recurrent input: sum of W_rec columns for neurons that spiked last step
        float rec = 0.f;
#pragma unroll
        for (int w = 0; w < 16; ++w) {
            unsigned m = smask[buf][w];
            const float* col = WTn + (size_t)(w << 5) * N_;
            while (m) {
                int bit = __ffs((int)m) - 1;
                m &= (m - 1);
                rec += __ldg(col + ((size_t)bit << 9));
            }
        }

        r = r * e_syn + rec;
        psc = psc * e_syn + KP * r;
        float I = It + psc + asc;
        v = v + a_mem * (VR - v) + a_mem * I;
        bool inref = rcnt > 0;
        if (inref) v = VR;
        float s = (v - VTH >= 0.0f) ? 1.0f : 0.0f;
        if (s > 0.0f) { v = VR; rcnt = 5; }
        else          { rcnt = inref ? rcnt - 1 : 0; }
        asc = asc * e_asc + AA * s;
        f = (t == 0) ? s : (alpha * f + oma * s);
        if (t >= startT) fsum += f;

        if (writeHist) {
            size_t idx = (size_t)t * (B_ * N_) + (size_t)b * N_ + n;
            spk[idx] = s; vlt[idx] = v; pscO[idx] = psc; filt[idx] = f;
        }

        unsigned bal = __ballot_sync(0xffffffffu, s > 0.0f);
        if (lane == 0) smask[buf ^ 1][wid] = bal;
        __syncthreads();
    }

    // readout: out[b,o] = (mean_t filtered) * out_scale @ W_out^T + b_out
    float cnt = (float)(T - startT);
    float a = (fsum / cnt) * __ldg(osc_p);
#pragma unroll 1
    for (int o = 0; o < O_; ++o) {
        float val = a * __ldg(Wout + (size_t)o * N_ + n);
#pragma unroll
        for (int off = 16; off > 0; off >>= 1)
            val += __shfl_down_sync(0xffffffffu, val, off);
        if (lane == 0) sred[wid] = val;
        __syncthreads();
        if (wid == 0) {
            float x2 = (lane < 16) ? sred[lane] : 0.0f;
#pragma unroll
            for (int off = 8; off > 0; off >>= 1)
                x2 += __shfl_down_sync(0xffffffffu, x2, off);
            if (lane == 0) out[b * O_ + o] = x2 + __ldg(bout + o);
        }
        __syncthreads();
    }
}

extern "C" void kernel_launch(void* const* d_in, const int* in_sizes, int n_in,
                              void* d_out, int out_size) {
    const float* x    = (const float*)d_in[0];
    const float* Win  = (const float*)d_in[1];
    const float* isc  = (const float*)d_in[2];
    const float* Wrec = (const float*)d_in[3];
    const float* Wout = (const float*)d_in[4];
    const float* bout = (const float*)d_in[5];
    const float* osc  = (const float*)d_in[6];

    const int T = in_sizes[0] / (B_ * D_);
    float* out = (float*)d_out;
    const size_t TBN = (size_t)T * B_ * N_;
    const long long fullsz = (long long)B_ * O_ + 4LL * (long long)TBN;
    const int writeHist = ((long long)out_size >= fullsz) ? 1 : 0;
    float* spk = out + B_ * O_;
    float* vlt = spk + TBN;
    float* psc = vlt + TBN;
    float* flt = psc + TBN;

    // constants exactly as JAX computes them (exp of the f32-rounded argument)
    const float e_syn = (float)exp((double)(-1.0f / 5.0f));
    const float e_asc = (float)exp((double)(-1.0f / 700.0f));
    const float alpha = (float)exp((double)(-1.0f / 20.0f));
    // NB: int(T * (1.0 - 0.8)) truncates to 199 for T=1000 (float artifact) -> 801-step window
    const int startT = (int)((double)T * (1.0 - 0.8));

    wt_transpose<<<dim3(16, 16), dim3(32, 8)>>>(Wrec);

    cudaFuncSetAttribute(iext_gemm, cudaFuncAttributeMaxDynamicSharedMemorySize, GEMM_SMEM);
    iext_gemm<<<dim3((T * B_) / GBM, N_ / GBN), 256, GEMM_SMEM>>>(x, Win, isc);

    sim_kernel<<<B_, N_>>>(Wout, bout, osc, out, spk, vlt, psc, flt,
                           T, startT, writeHist, e_syn, e_asc, alpha);
}

// round 3
// speedup vs baseline: 1.6060x; 1.6060x over previous
#include <cuda_runtime.h>
#include <math.h>

#define T_MAX 1000
#define B_ 64
#define D_ 128
#define N_ 512
#define O_ 10

// scratch (device globals: no allocation allowed in kernel_launch)
__device__ float g_Iext[(size_t)T_MAX * B_ * N_];  // 131 MB
__device__ float g_WT[N_ * N_];                    // W_rec transposed: g_WT[m][n] = W_rec[n][m]

// ---------------- transpose W_rec -> g_WT ----------------
__global__ void wt_transpose(const float* __restrict__ W) {
    __shared__ float tile[32][33];
    int bx = blockIdx.x * 32, by = blockIdx.y * 32;
    int tx = threadIdx.x, ty = threadIdx.y;
#pragma unroll
    for (int i = 0; i < 32; i += 8)
        tile[ty + i][tx] = W[(size_t)(by + ty + i) * N_ + (bx + tx)];
    __syncthreads();
#pragma unroll
    for (int i = 0; i < 32; i += 8)
        g_WT[(size_t)(bx + ty + i) * N_ + (by + tx)] = tile[tx][ty + i];
}

// ---------------- I_ext GEMM: (T*B,128) x (128,512) fp32, packed f32x2 FMA ----------------
#define GBM 128
#define GBN 128
#define GK  128
#define A_LD 132
#define B_LD 130
#define GEMM_SMEM ((GBM * A_LD + GK * B_LD) * 4)

__global__ __launch_bounds__(256) void iext_gemm(const float* __restrict__ X,
                                                 const float* __restrict__ Win,
                                                 const float* __restrict__ sc_p) {
    extern __shared__ float sm[];
    float* As = sm;                 // [GBM][A_LD]  m-major
    float* Bs = sm + GBM * A_LD;    // [GK][B_LD]   k-major (W_in transposed)
    const float sc = __ldg(sc_p);
    const int m0 = blockIdx.x * GBM;
    const int n0 = blockIdx.y * GBN;
    const int tid = threadIdx.x;
    const int lane4 = (tid & 31) * 4;
    const int wrp = tid >> 5;

#pragma unroll
    for (int p = 0; p < 16; ++p) {
        int m = wrp + p * 8;
        float4 xv = *(const float4*)(X + (size_t)(m0 + m) * D_ + lane4);
        xv.x *= sc; xv.y *= sc; xv.z *= sc; xv.w *= sc;
        *(float4*)(As + m * A_LD + lane4) = xv;
    }
#pragma unroll
    for (int p = 0; p < 16; ++p) {
        int nn = wrp + p * 8;
        float4 wv = *(const float4*)(Win + (size_t)(n0 + nn) * D_ + lane4);
        Bs[(lane4 + 0) * B_LD + nn] = wv.x;
        Bs[(lane4 + 1) * B_LD + nn] = wv.y;
        Bs[(lane4 + 2) * B_LD + nn] = wv.z;
        Bs[(lane4 + 3) * B_LD + nn] = wv.w;
    }
    __syncthreads();

    const int tm  = (tid >> 4) * 8;   // 8 M-rows per thread
    const int tn2 = (tid & 15) * 2;   // 8 N-cols as 4 float2 at stride 32 (bank-conflict-free)
    unsigned long long acc[8][4];
#pragma unroll
    for (int i = 0; i < 8; ++i)
#pragma unroll
        for (int j = 0; j < 4; ++j) acc[i][j] = 0ull;

#pragma unroll 2
    for (int k = 0; k < GK; ++k) {
        unsigned long long b2[4];
#pragma unroll
        for (int j = 0; j < 4; ++j) {
            float2 bb = *(const float2*)(Bs + k * B_LD + tn2 + 32 * j);
            asm("mov.b64 %0, {%1,%2};" : "=l"(b2[j]) : "f"(bb.x), "f"(bb.y));
        }
#pragma unroll
        for (int i = 0; i < 8; ++i) {
            float a = As[(tm + i) * A_LD + k];
            unsigned long long a2;
            asm("mov.b64 %0, {%1,%1};" : "=l"(a2) : "f"(a));
#pragma unroll
            for (int j = 0; j < 4; ++j)
                asm("fma.rn.f32x2 %0, %1, %2, %0;" : "+l"(acc[i][j]) : "l"(a2), "l"(b2[j]));
        }
    }
#pragma unroll
    for (int i = 0; i < 8; ++i) {
        float* orow = g_Iext + (size_t)(m0 + tm + i) * N_ + n0 + tn2;
#pragma unroll
        for (int j = 0; j < 4; ++j) {
            float2 o;
            asm("mov.b64 {%0,%1}, %2;" : "=f"(o.x), "=f"(o.y) : "l"(acc[i][j]));
            *(float2*)(orow + 32 * j) = o;
        }
    }
}

// ---------------- recurrent GLIF3 simulation: 1 CTA per batch, 1 thread per neuron ----------------
__global__ __launch_bounds__(512, 1) void sim_kernel(
    const float* __restrict__ Wout, const float* __restrict__ bout,
    const float* __restrict__ osc_p,
    float* __restrict__ out, float* __restrict__ spk, float* __restrict__ vlt,
    float* __restrict__ pscO, float* __restrict__ filt,
    int T, int startT, int writeHist,
    float e_syn, float e_asc, float alpha)
{
    const int b = blockIdx.x;
    const int n = threadIdx.x;
    const int wid = n >> 5, lane = n & 31;
    // 3-phase rotation: read buf rb, producers write wb=(rb+1)%3, thread0 resets zb=(rb+2)%3.
    // All three roles distinct each step -> one __syncthreads per step is sufficient.
    __shared__ unsigned smask[3][16];
    __shared__ unsigned sany[3];
    __shared__ float sred[16];
    if (n < 16) { smask[0][n] = 0u; smask[1][n] = 0u; smask[2][n] = 0u; }
    if (n < 3) sany[n] = 0u;
    __syncthreads();

    const float a_mem = 0.05f, VR = -60.0f, VTH = -45.0f, KP = 0.2f, AA = -0.2f;
    const float oma = 1.0f - alpha;
    float v = VR, asc = 0.f, r = 0.f, psc = 0.f, f = 0.f, fsum = 0.f;
    int rcnt = 0;
    const float* Ibase = g_Iext + (size_t)b * N_ + n;
    const float* WTn = g_WT + n;
    const int BN = B_ * N_;

    // 4-deep I_ext register prefetch pipeline
    float pre[4];
#pragma unroll
    for (int j = 0; j < 4; ++j)
        pre[j] = (j < T) ? __ldg(Ibase + (size_t)j * BN) : 0.f;

    int rb = 0;
    const int Tm = T & ~3;
    for (int t0 = 0; t0 < Tm; t0 += 4) {
#pragma unroll
        for (int j = 0; j < 4; ++j) {
            const int tt = t0 + j;
            const float It = pre[j];
            const int tn = tt + 4;
            if (tn < T) pre[j] = __ldg(Ibase + (size_t)tn * BN);

            const int wb = (rb == 2) ? 0 : rb + 1;
            const int zb = (wb == 2) ? 0 : wb + 1;

            float rec = 0.f;
            if (sany[rb]) {
#pragma unroll
                for (int w = 0; w < 16; ++w) {
                    unsigned m = smask[rb][w];
                    const float* col = WTn + (size_t)(w << 5) * N_;
                    while (m) {
                        int bit = __ffs((int)m) - 1;
                        m &= (m - 1);
                        rec += __ldg(col + ((size_t)bit << 9));
                    }
                }
            }

            r = r * e_syn + rec;
            psc = psc * e_syn + KP * r;
            v = v + a_mem * (VR - v) + a_mem * (It + psc + asc);
            bool inref = rcnt > 0;
            if (inref) v = VR;
            float s = (v - VTH >= 0.0f) ? 1.0f : 0.0f;
            if (s > 0.0f) { v = VR; rcnt = 5; }
            else          { rcnt = inref ? rcnt - 1 : 0; }
            asc = asc * e_asc + AA * s;
            f = (tt == 0) ? s : (alpha * f + oma * s);
            if (tt >= startT) fsum += f;

            if (writeHist) {
                size_t idx = (size_t)tt * BN + (size_t)b * N_ + n;
                spk[idx] = s; vlt[idx] = v; pscO[idx] = psc; filt[idx] = f;
            }

            unsigned bal = __ballot_sync(0xffffffffu, s > 0.0f);
            if (lane == 0) {
                smask[wb][wid] = bal;
                if (bal) atomicOr(&sany[wb], 1u);
            }
            if (n == 0) sany[zb] = 0u;
            __syncthreads();
            rb = wb;
        }
    }
    // remainder steps (T not multiple of 4): latency-exposed loads, <=3 steps
    for (int tt = Tm; tt < T; ++tt) {
        const float It = __ldg(Ibase + (size_t)tt * BN);
        const int wb = (rb == 2) ? 0 : rb + 1;
        const int zb = (wb == 2) ? 0 : wb + 1;
        float rec = 0.f;
        if (sany[rb]) {
#pragma unroll
            for (int w = 0; w < 16; ++w) {
                unsigned m = smask[rb][w];
                const float* col = WTn + (size_t)(w << 5) * N_;
                while (m) {
                    int bit = __ffs((int)m) - 1;
                    m &= (m - 1);
                    rec += __ldg(col + ((size_t)bit << 9));
                }
            }
        }
        r = r * e_syn + rec;
        psc = psc * e_syn + KP * r;
        v = v + a_mem * (VR - v) + a_mem * (It + psc + asc);
        bool inref = rcnt > 0;
        if (inref) v = VR;
        float s = (v - VTH >= 0.0f) ? 1.0f : 0.0f;
        if (s > 0.0f) { v = VR; rcnt = 5; }
        else          { rcnt = inref ? rcnt - 1 : 0; }
        asc = asc * e_asc + AA * s;
        f = (tt == 0) ? s : (alpha * f + oma * s);
        if (tt >= startT) fsum += f;
        if (writeHist) {
            size_t idx = (size_t)tt * BN + (size_t)b * N_ + n;
            spk[idx] = s; vlt[idx] = v; pscO[idx] = psc; filt[idx] = f;
        }
        unsigned bal = __ballot_sync(0xffffffffu, s > 0.0f);
        if (lane == 0) {
            smask[wb][wid] = bal;
            if (bal) atomicOr(&sany[wb], 1u);
        }
        if (n == 0) sany[zb] = 0u;
        __syncthreads();
        rb = wb;
    }

    // readout: out[b,o] = (mean_t filtered) * out_scale @ W_out^T + b_out
    float cnt = (float)(T - startT);
    float a = (fsum / cnt) * __ldg(osc_p);
#pragma unroll 1
    for (int o = 0; o < O_; ++o) {
        float val = a * __ldg(Wout + (size_t)o * N_ + n);
#pragma unroll
        for (int off = 16; off > 0; off >>= 1)
            val += __shfl_down_sync(0xffffffffu, val, off);
        if (lane == 0) sred[wid] = val;
        __syncthreads();
        if (wid == 0) {
            float x2 = (lane < 16) ? sred[lane] : 0.0f;
#pragma unroll
            for (int off = 8; off > 0; off >>= 1)
                x2 += __shfl_down_sync(0xffffffffu, x2, off);
            if (lane == 0) out[b * O_ + o] = x2 + __ldg(bout + o);
        }
        __syncthreads();
    }
}

extern "C" void kernel_launch(void* const* d_in, const int* in_sizes, int n_in,
                              void* d_out, int out_size) {
    const float* x    = (const float*)d_in[0];
    const float* Win  = (const float*)d_in[1];
    const float* isc  = (const float*)d_in[2];
    const float* Wrec = (const float*)d_in[3];
    const float* Wout = (const float*)d_in[4];
    const float* bout = (const float*)d_in[5];
    const float* osc  = (const float*)d_in[6];

    const int T = in_sizes[0] / (B_ * D_);
    float* out = (float*)d_out;
    const size_t TBN = (size_t)T * B_ * N_;
    const long long fullsz = (long long)B_ * O_ + 4LL * (long long)TBN;
    const int writeHist = ((long long)out_size >= fullsz) ? 1 : 0;
    float* spk = out + B_ * O_;
    float* vlt = spk + TBN;
    float* psc = vlt + TBN;
    float* flt = psc + TBN;

    // constants exactly as JAX computes them (exp of the f32-rounded argument)
    const float e_syn = (float)exp((double)(-1.0f / 5.0f));
    const float e_asc = (float)exp((double)(-1.0f / 700.0f));
    const float alpha = (float)exp((double)(-1.0f / 20.0f));
    // NB: int(T * (1.0 - 0.8)) truncates to 199 for T=1000 (float artifact) -> 801-step window
    const int startT = (int)((double)T * (1.0 - 0.8));

    // order: gemm, transpose, sim  (ncu -s 5 -c 1 then lands on sim in replay #2)
    cudaFuncSetAttribute(iext_gemm, cudaFuncAttributeMaxDynamicSharedMemorySize, GEMM_SMEM);
    iext_gemm<<<dim3((T * B_) / GBM, N_ / GBN), 256, GEMM_SMEM>>>(x, Win, isc);

    wt_transpose<<<dim3(16, 16), dim3(32, 8)>>>(Wrec);

    sim_kernel<<<B_, N_>>>(Wout, bout, osc, out, spk, vlt, psc, flt,
                           T, startT, writeHist, e_syn, e_asc, alpha);
}